// round 15
// baseline (speedup 1.0000x reference)
#include <cuda_runtime.h>

#define Bc 8
#define Cc 96
#define Hc 256
#define Wc 256
#define TH 16
#define VR2 18                 // vsum/bp rows: img rowBase-1 .. rowBase+16 (vr = g-rowBase+1)
#define NU 264                 // walk column units: col c = u - 4
#define RFq 33                 // quads per half-row
#define RFf 132                // floats per half-row
#define HOFq 596               // mf/hf half offset (quads): 2384 floats, %32 = 16
#define HOFf 2384
#define PQ 1192                // mf/hf pair size (quads)
#define LHOFq 660              // lo half offset (quads): 20 rows * 33; 2640 floats, %32 = 16
#define LHOFf 2640
#define FULLM 0xffffffffu

// reciprocal of valid-count for avgpool (count_include_pad=False); 0 outside image
__device__ __forceinline__ float rcnt0(int i, int p) {
    if (i < 0 || i > Hc - 1) return 0.f;
    int lo = i - p; if (lo < 0) lo = 0;
    int hi = i + p; if (hi > Hc - 1) hi = Hc - 1;
    return __fdividef(1.f, (float)(hi - lo + 1));
}

__device__ __forceinline__ float bn_silu(float acc, float scal, float shft) {
    float v = fmaf(acc, scal, shft);
    return v * __fdividef(1.f, 1.f + __expf(-v));
}

// full 16-col window (cols 8J-4..8J+11), pair at pq with half offset HOq
__device__ __forceinline__ void ld16p(const float4* __restrict__ pq, int row, int J,
                                      float* __restrict__ d) {
    const float4* r = pq + row * RFq;
    float4 A0 = r[J];
    float4 B0 = r[HOFq + J];
    float4 A1 = r[J + 1];
    float4 B1 = r[HOFq + J + 1];
    d[0]=A0.x; d[1]=A0.y; d[2]=A0.z;  d[3]=A0.w;
    d[4]=B0.x; d[5]=B0.y; d[6]=B0.z;  d[7]=B0.w;
    d[8]=A1.x; d[9]=A1.y; d[10]=A1.z; d[11]=A1.w;
    d[12]=B1.x; d[13]=B1.y; d[14]=B1.z; d[15]=B1.w;
}

// 10-col window (cols 8J-1..8J+8): 2 LDS.128 + 2 shfl + edge fixups. Warp-converged.
__device__ __forceinline__ void ld10s(const float4* __restrict__ pq, int row, int J,
                                      int HOq, int HOf, float* __restrict__ d) {
    const float* pf = (const float*)pq;
    float4 B0 = pq[HOq + row * RFq + J];        // cols 8J..8J+3
    float4 A1 = pq[row * RFq + J + 1];          // cols 8J+4..8J+7
    float lw = __shfl_up_sync(FULLM, A1.w, 1);
    float rw = __shfl_down_sync(FULLM, B0.x, 1);
    if (J == 0)  lw = pf[row * RFf + 3];            // A[0].w = col -1 (zero halo)
    if (J == 31) rw = pf[HOf + row * RFf + 128];    // B[32].x = col 256 (zero halo)
    d[0]=lw;
    d[1]=B0.x; d[2]=B0.y; d[3]=B0.z; d[4]=B0.w;
    d[5]=A1.x; d[6]=A1.y; d[7]=A1.z; d[8]=A1.w;
    d[9]=rw;
}

// 12-col window (cols 8J-2..8J+9): 2 LDS.128 + 4 shfl + edge fixups. Warp-converged.
__device__ __forceinline__ void ld12s(const float4* __restrict__ pq, int row, int J,
                                      int HOq, int HOf, float* __restrict__ d) {
    const float* pf = (const float*)pq;
    float4 B0 = pq[HOq + row * RFq + J];        // cols 8J..8J+3
    float4 A1 = pq[row * RFq + J + 1];          // cols 8J+4..8J+7
    float l2 = __shfl_up_sync(FULLM, A1.z, 1);  // col 8J-2
    float l1 = __shfl_up_sync(FULLM, A1.w, 1);  // col 8J-1
    float r1 = __shfl_down_sync(FULLM, B0.x, 1);// col 8J+8
    float r2 = __shfl_down_sync(FULLM, B0.y, 1);// col 8J+9
    if (J == 0)  { l2 = pf[row * RFf + 2]; l1 = pf[row * RFf + 3]; }
    if (J == 31) { r1 = pf[HOf + row * RFf + 128]; r2 = pf[HOf + row * RFf + 129]; }
    d[0]=l2; d[1]=l1;
    d[2]=B0.x; d[3]=B0.y; d[4]=B0.z; d[5]=B0.w;
    d[6]=A1.x; d[7]=A1.y; d[8]=A1.z; d[9]=A1.w;
    d[10]=r1; d[11]=r2;
}

// 3x3 conv, 8-wide x 2 rows, narrowed rows (mf path).
__device__ __forceinline__ void conv3_shfl8(const float4* __restrict__ pq, int s0, int J,
                                            const float* __restrict__ sw,
                                            float inv, float shft,
                                            float* __restrict__ outp, int gy0) {
    float w[9];
#pragma unroll
    for (int i = 0; i < 9; i++) w[i] = sw[i];
    float a0[8] = {0,0,0,0,0,0,0,0}, a1[8] = {0,0,0,0,0,0,0,0};
#pragma unroll
    for (int r = 0; r < 4; r++) {
        float c[10];
        ld10s(pq, s0 + r, J, HOFq, HOFf, c);
        if (r < 3) {
#pragma unroll
            for (int kc = 0; kc < 3; kc++) {
                float wv = w[r * 3 + kc];
#pragma unroll
                for (int p = 0; p < 8; p++) a0[p] = fmaf(wv, c[p + kc], a0[p]);
            }
        }
        if (r >= 1) {
#pragma unroll
            for (int kc = 0; kc < 3; kc++) {
                float wv = w[(r - 1) * 3 + kc];
#pragma unroll
                for (int p = 0; p < 8; p++) a1[p] = fmaf(wv, c[p + kc], a1[p]);
            }
        }
    }
    float4 o;
    o.x = bn_silu(a0[0], inv, shft); o.y = bn_silu(a0[1], inv, shft);
    o.z = bn_silu(a0[2], inv, shft); o.w = bn_silu(a0[3], inv, shft);
    *(float4*)(outp + (size_t)gy0 * Wc) = o;
    o.x = bn_silu(a0[4], inv, shft); o.y = bn_silu(a0[5], inv, shft);
    o.z = bn_silu(a0[6], inv, shft); o.w = bn_silu(a0[7], inv, shft);
    *(float4*)(outp + (size_t)gy0 * Wc + 4) = o;
    o.x = bn_silu(a1[0], inv, shft); o.y = bn_silu(a1[1], inv, shft);
    o.z = bn_silu(a1[2], inv, shft); o.w = bn_silu(a1[3], inv, shft);
    *(float4*)(outp + (size_t)(gy0 + 1) * Wc) = o;
    o.x = bn_silu(a1[4], inv, shft); o.y = bn_silu(a1[5], inv, shft);
    o.z = bn_silu(a1[6], inv, shft); o.w = bn_silu(a1[7], inv, shft);
    *(float4*)(outp + (size_t)(gy0 + 1) * Wc + 4) = o;
}

__global__ __launch_bounds__(256, 5) void trifreq_kernel(
    const float* __restrict__ x,
    const float* __restrict__ w_lo,
    const float* __restrict__ w_mf,
    const float* __restrict__ w_hf,
    const float* __restrict__ bn_gamma,
    const float* __restrict__ bn_beta,
    const float* __restrict__ bn_mean,
    const float* __restrict__ bn_var,
    float* __restrict__ out)
{
    __shared__ float4 s_buf[2 * PQ];   // lo: raw pair (20 rows, half 660q); mf: v3|v7 pairs;
                                       // hf: raw|v3 pairs
    __shared__ float s_w[25];

    const int t = threadIdx.x;
    const int tileY = blockIdx.x;
    const int ch = blockIdx.y;
    const int b = blockIdx.z;
    const int group = ch >> 5;
    const int k = ch & 31;
    const int rowBase = tileY * TH;

    if (group == 0)      { if (t < 25) s_w[t] = w_lo[k * 25 + t]; }
    else if (group == 1) { if (t < 9)  s_w[t] = w_mf[k * 9 + t]; }
    else                 { if (t < 9)  s_w[t] = w_hf[k * 9 + t]; }

    const float* xp = x + (size_t)(b * Cc + ch) * Hc * Wc;

    // img row for walk slot s is rowBase + s - 4
#define LDR(slot) ((colOK && (unsigned)(rowBase + (slot) - 4) < (unsigned)Hc) \
                   ? colp[(size_t)(rowBase + (slot) - 4) * Wc] : 0.f)

    if (group == 0) {
        // ---- lo load: 20 raw rows (img rowBase-2..+17) into pair layout ----
        for (int rr = t >> 4; rr < 20; rr += 16) {
            int gr = rowBase + rr - 2;
            bool rowOK = (unsigned)gr < (unsigned)Hc;
            const float* rowp = xp + gr * Wc;
            for (int qq = (t & 15); qq < 66; qq += 16) {
                float4 v = make_float4(0.f, 0.f, 0.f, 0.f);
                if (qq >= 1 && qq <= 64 && rowOK)
                    v = *(const float4*)(rowp + (qq - 1) * 4);
                s_buf[(qq & 1) * LHOFq + rr * RFq + (qq >> 1)] = v;
            }
        }
    } else if (group == 1) {
        // ---- mf walk: preload 24 rows, fused v3/v7 into pairs ----
        float* v3f = (float*)s_buf;
        float* v7f = (float*)(s_buf + PQ);
        for (int u = t; u < NU; u += 256) {
            int c = u - 4;
            bool colOK = (unsigned)c < (unsigned)Wc;
            const float* colp = xp + c;
            int quad = u >> 2;
            int cb = (quad & 1) * HOFf + ((quad >> 1) << 2) + (u & 3);
            float rv[24];
#pragma unroll
            for (int s = 0; s < 24; s++) rv[s] = LDR(s);
            float s3 = rv[2] + rv[3] + rv[4];
            float s7 = rv[0]+rv[1]+rv[2]+rv[3]+rv[4]+rv[5]+rv[6];
            v3f[cb] = s3; v7f[cb] = s7;
#pragma unroll
            for (int vr = 1; vr <= 17; vr++) {
                s3 += rv[vr + 4] - rv[vr + 1];
                s7 += rv[vr + 6] - rv[vr - 1];
                v3f[cb + vr * RFf] = s3;
                v7f[cb + vr * RFf] = s7;
            }
        }
    } else {
        // ---- hf walk: preload 20 rows; raw pair rows 0..17 + v3 pair ----
        float* rawf = (float*)s_buf;
        float* v3f = (float*)(s_buf + PQ);
        for (int u = t; u < NU; u += 256) {
            int c = u - 4;
            bool colOK = (unsigned)c < (unsigned)Wc;
            const float* colp = xp + c;
            int quad = u >> 2;
            int cb = (quad & 1) * HOFf + ((quad >> 1) << 2) + (u & 3);
            float rv[20];
#pragma unroll
            for (int s = 0; s < 20; s++) rv[s] = LDR(s + 2);   // img rowBase-2..+17
#pragma unroll
            for (int r = 0; r < 18; r++) rawf[cb + r * RFf] = rv[r + 1];   // raw row r = img rowBase+r-1
#pragma unroll
            for (int vr = 0; vr < 18; vr++)
                v3f[cb + vr * RFf] = rv[vr] + rv[vr + 1] + rv[vr + 2];     // centered img rowBase+vr-1
        }
    }
    __syncthreads();

    const int oc = 3 * k + group;                 // channel shuffle folded in
    const float inv  = bn_gamma[oc] * rsqrtf(bn_var[oc] + 1e-5f);
    const float shft = bn_beta[oc] - bn_mean[oc] * inv;

    const int J = t & 31;          // 8-col segment: cols 8J..8J+7
    const int warpid = t >> 5;

    if (group == 0) {
        // ===== lo: 5x5 dwconv, 8-wide scatter, two weight passes =====
        const int band = warpid;                  // rows gy0, gy0+1
        const int gy0 = rowBase + 2 * band;
        float* outp = out + (size_t)(b * Cc + oc) * Hc * Wc + J * 8;
        float a0[8] = {0,0,0,0,0,0,0,0}, a1[8] = {0,0,0,0,0,0,0,0};
        {   // pass 1: weight rows 0..2, buffer rows 2band..2band+3
            float wr[15];
#pragma unroll
            for (int i = 0; i < 15; i++) wr[i] = s_w[i];
#pragma unroll
            for (int rr = 0; rr < 4; rr++) {
                float c[12];
                ld12s(s_buf, 2 * band + rr, J, LHOFq, LHOFf, c);
                if (rr <= 2) {
#pragma unroll
                    for (int kc = 0; kc < 5; kc++) {
                        float wv = wr[rr * 5 + kc];
#pragma unroll
                        for (int p = 0; p < 8; p++) a0[p] = fmaf(wv, c[p + kc], a0[p]);
                    }
                }
                if (rr >= 1) {
#pragma unroll
                    for (int kc = 0; kc < 5; kc++) {
                        float wv = wr[(rr - 1) * 5 + kc];
#pragma unroll
                        for (int p = 0; p < 8; p++) a1[p] = fmaf(wv, c[p + kc], a1[p]);
                    }
                }
            }
        }
        {   // pass 2: weight rows 3..4, buffer rows 2band+3..2band+5
            float wr[10];
#pragma unroll
            for (int i = 0; i < 10; i++) wr[i] = s_w[15 + i];
#pragma unroll
            for (int rr2 = 0; rr2 < 3; rr2++) {
                float c[12];
                ld12s(s_buf, 2 * band + 3 + rr2, J, LHOFq, LHOFf, c);
                if (rr2 <= 1) {
#pragma unroll
                    for (int kc = 0; kc < 5; kc++) {
                        float wv = wr[rr2 * 5 + kc];
#pragma unroll
                        for (int p = 0; p < 8; p++) a0[p] = fmaf(wv, c[p + kc], a0[p]);
                    }
                }
                if (rr2 >= 1) {
#pragma unroll
                    for (int kc = 0; kc < 5; kc++) {
                        float wv = wr[(rr2 - 1) * 5 + kc];
#pragma unroll
                        for (int p = 0; p < 8; p++) a1[p] = fmaf(wv, c[p + kc], a1[p]);
                    }
                }
            }
        }
        float4 o;
        o.x = bn_silu(a0[0], inv, shft); o.y = bn_silu(a0[1], inv, shft);
        o.z = bn_silu(a0[2], inv, shft); o.w = bn_silu(a0[3], inv, shft);
        *(float4*)(outp + (size_t)gy0 * Wc) = o;
        o.x = bn_silu(a0[4], inv, shft); o.y = bn_silu(a0[5], inv, shft);
        o.z = bn_silu(a0[6], inv, shft); o.w = bn_silu(a0[7], inv, shft);
        *(float4*)(outp + (size_t)gy0 * Wc + 4) = o;
        o.x = bn_silu(a1[0], inv, shft); o.y = bn_silu(a1[1], inv, shft);
        o.z = bn_silu(a1[2], inv, shft); o.w = bn_silu(a1[3], inv, shft);
        *(float4*)(outp + (size_t)(gy0 + 1) * Wc) = o;
        o.x = bn_silu(a1[4], inv, shft); o.y = bn_silu(a1[5], inv, shft);
        o.z = bn_silu(a1[6], inv, shft); o.w = bn_silu(a1[7], inv, shft);
        *(float4*)(outp + (size_t)(gy0 + 1) * Wc + 4) = o;
        return;
    }

    if (group == 1) {
        // ===== mf: band-pass once, 8-wide, in-place over v3 pair (R14-proven) =====
        float icx7[8];
#pragma unroll
        for (int m = 0; m < 8; m++) {
            int c = 8 * J + m;
            int cnt = (c < 3 ? c : 3) + (255 - c < 3 ? 255 - c : 3) + 1;
            icx7[m] = __fdividef(1.f, (float)cnt);
        }
        for (int vr = warpid; vr < VR2; vr += 8) {
            int g = rowBase + vr - 1;
            float iy3 = rcnt0(g, 1), iy7 = rcnt0(g, 3);
            float c3[10], u7[16], bp[8];
            ld10s(s_buf, vr, J, HOFq, HOFf, c3);   // v3 cols 8J-1..8J+8
            ld16p(s_buf + PQ, vr, J, u7);          // v7 cols 8J-4..8J+11
            float h3 = c3[0] + c3[1] + c3[2];      // col 8J
#pragma unroll
            for (int m = 0; m < 8; m++) {
                int c = 8 * J + m;
                float ic3 = (c == 0 || c == 255) ? 0.5f : (1.f / 3.f);
                bp[m] = h3 * (ic3 * iy3);
                if (m < 7) h3 += c3[m + 3] - c3[m];
            }
            float h7 = u7[1]+u7[2]+u7[3]+u7[4]+u7[5]+u7[6]+u7[7];   // col 8J
#pragma unroll
            for (int m = 0; m < 8; m++) {
                bp[m] -= h7 * (icx7[m] * iy7);
                if (m < 7) h7 += u7[m + 8] - u7[m + 1];
            }
            __syncwarp();                          // row reads complete before overwrite
            float4 o;
            o.x = bp[0]; o.y = bp[1]; o.z = bp[2]; o.w = bp[3];
            s_buf[HOFq + vr * RFq + J] = o;        // B[J] (cols 8J..8J+3)
            o.x = bp[4]; o.y = bp[5]; o.z = bp[6]; o.w = bp[7];
            s_buf[vr * RFq + J + 1] = o;           // A[J+1] (cols 8J+4..8J+7)
        }
        __syncthreads();
        {
            float* outp = out + (size_t)(b * Cc + oc) * Hc * Wc + J * 8;
            conv3_shfl8(s_buf, 2 * warpid, J, s_w, inv, shft, outp, rowBase + 2 * warpid);
        }
        return;
    }

    // ===== hf: fused high-pass + 3x3 conv (no hp buffer, no second barrier) =====
    {
        const int band = warpid;
        const int gy0 = rowBase + 2 * band;
        float* outp = out + (size_t)(b * Cc + oc) * Hc * Wc + J * 8;
        float a0[8] = {0,0,0,0,0,0,0,0}, a1[8] = {0,0,0,0,0,0,0,0};
#pragma unroll
        for (int r = 0; r < 4; r++) {
            int vr = 2 * band + r;                 // hp row (bp-space 0..17)
            int g = rowBase + vr - 1;
            float iy3 = rcnt0(g, 1);
            float c3[10], hp[8];
            ld10s(s_buf + PQ, vr, J, HOFq, HOFf, c3);  // v3 cols 8J-1..8J+8
            float4 R0 = s_buf[HOFq + vr * RFq + J];    // raw cols 8J..8J+3
            float4 R1 = s_buf[vr * RFq + J + 1];       // raw cols 8J+4..8J+7
            float ur[8] = {R0.x, R0.y, R0.z, R0.w, R1.x, R1.y, R1.z, R1.w};
            float h3 = c3[0] + c3[1] + c3[2];          // col 8J
#pragma unroll
            for (int m = 0; m < 8; m++) {
                int c = 8 * J + m;
                float ic3 = (c == 0 || c == 255) ? 0.5f : (1.f / 3.f);
                hp[m] = ur[m] - h3 * (ic3 * iy3);
                if (m < 7) h3 += c3[m + 3] - c3[m];
            }
            // conv-edge hp values from neighbor lanes (converged); image edges are zero pad
            float lw = __shfl_up_sync(FULLM, hp[7], 1);    // col 8J-1
            float rw = __shfl_down_sync(FULLM, hp[0], 1);  // col 8J+8
            if (J == 0)  lw = 0.f;
            if (J == 31) rw = 0.f;
            float c[10];
            c[0] = lw;
#pragma unroll
            for (int m = 0; m < 8; m++) c[m + 1] = hp[m];
            c[9] = rw;
            if (r < 3) {
#pragma unroll
                for (int kc = 0; kc < 3; kc++) {
                    float wv = s_w[r * 3 + kc];
#pragma unroll
                    for (int p = 0; p < 8; p++) a0[p] = fmaf(wv, c[p + kc], a0[p]);
                }
            }
            if (r >= 1) {
#pragma unroll
                for (int kc = 0; kc < 3; kc++) {
                    float wv = s_w[(r - 1) * 3 + kc];
#pragma unroll
                    for (int p = 0; p < 8; p++) a1[p] = fmaf(wv, c[p + kc], a1[p]);
                }
            }
        }
        float4 o;
        o.x = bn_silu(a0[0], inv, shft); o.y = bn_silu(a0[1], inv, shft);
        o.z = bn_silu(a0[2], inv, shft); o.w = bn_silu(a0[3], inv, shft);
        *(float4*)(outp + (size_t)gy0 * Wc) = o;
        o.x = bn_silu(a0[4], inv, shft); o.y = bn_silu(a0[5], inv, shft);
        o.z = bn_silu(a0[6], inv, shft); o.w = bn_silu(a0[7], inv, shft);
        *(float4*)(outp + (size_t)gy0 * Wc + 4) = o;
        o.x = bn_silu(a1[0], inv, shft); o.y = bn_silu(a1[1], inv, shft);
        o.z = bn_silu(a1[2], inv, shft); o.w = bn_silu(a1[3], inv, shft);
        *(float4*)(outp + (size_t)(gy0 + 1) * Wc) = o;
        o.x = bn_silu(a1[4], inv, shft); o.y = bn_silu(a1[5], inv, shft);
        o.z = bn_silu(a1[6], inv, shft); o.w = bn_silu(a1[7], inv, shft);
        *(float4*)(outp + (size_t)(gy0 + 1) * Wc + 4) = o;
    }
}

extern "C" void kernel_launch(void* const* d_in, const int* in_sizes, int n_in,
                              void* d_out, int out_size) {
    (void)in_sizes; (void)n_in; (void)out_size;
    dim3 grid(Hc / TH, Cc, Bc);
    dim3 block(256);
    trifreq_kernel<<<grid, block>>>(
        (const float*)d_in[0], (const float*)d_in[1], (const float*)d_in[2],
        (const float*)d_in[3], (const float*)d_in[4], (const float*)d_in[5],
        (const float*)d_in[6], (const float*)d_in[7], (float*)d_out);
}